// round 1
// baseline (speedup 1.0000x reference)
#include <cuda_runtime.h>
#include <math.h>

#define BSZ 8
#define SEQ 1024
#define DIM 1024
#define NH 16
#define DH 64
#define MTOK (BSZ*SEQ)        // 8192
#define FFD  (2*DIM)          // 2048

// ---------------- scratch (device globals; no runtime allocation) ----------
__device__ float g_q[MTOK*DIM];
__device__ float g_k[MTOK*DIM];
__device__ float g_v[MTOK*DIM];
__device__ float g_attn[MTOK*DIM];
__device__ float g_h1[MTOK*DIM];
__device__ float g_ffn[MTOK*FFD];

// ---------------- generic NT GEMM: C = (A[M,K] * B[N,K]^T + bias)*scale (+res)(+relu)
__global__ __launch_bounds__(256) void gemm_nt(
    const float* __restrict__ A, const float* __restrict__ Bw,
    const float* __restrict__ bias, const float* __restrict__ res,
    float* __restrict__ C, int M, int N, int K, float scale, int relu)
{
    __shared__ float As[8][128];
    __shared__ float Bs[8][128];
    const int n0 = blockIdx.x * 128;
    const int m0 = blockIdx.y * 128;
    const int tid = threadIdx.x;
    const int tx = tid & 15, ty = tid >> 4;

    float acc[8][8];
#pragma unroll
    for (int i = 0; i < 8; i++)
#pragma unroll
        for (int j = 0; j < 8; j++) acc[i][j] = 0.f;

    const int lrow = tid >> 1;
    const int lc   = (tid & 1) * 4;
    const float* Aptr = A + (size_t)(m0 + lrow) * K + lc;
    const float* Bptr = Bw + (size_t)(n0 + lrow) * K + lc;

    for (int kt = 0; kt < K; kt += 8) {
        float4 av = *(const float4*)(Aptr + kt);
        float4 bv = *(const float4*)(Bptr + kt);
        As[lc+0][lrow] = av.x; As[lc+1][lrow] = av.y;
        As[lc+2][lrow] = av.z; As[lc+3][lrow] = av.w;
        Bs[lc+0][lrow] = bv.x; Bs[lc+1][lrow] = bv.y;
        Bs[lc+2][lrow] = bv.z; Bs[lc+3][lrow] = bv.w;
        __syncthreads();
#pragma unroll
        for (int k = 0; k < 8; k++) {
            float a[8], b[8];
            *(float4*)(a)     = *(const float4*)&As[k][ty*8];
            *(float4*)(a + 4) = *(const float4*)&As[k][ty*8 + 4];
            *(float4*)(b)     = *(const float4*)&Bs[k][tx*8];
            *(float4*)(b + 4) = *(const float4*)&Bs[k][tx*8 + 4];
#pragma unroll
            for (int i = 0; i < 8; i++)
#pragma unroll
                for (int j = 0; j < 8; j++)
                    acc[i][j] = fmaf(a[i], b[j], acc[i][j]);
        }
        __syncthreads();
    }

    // epilogue
#pragma unroll
    for (int i = 0; i < 8; i++) {
        const int m = m0 + ty*8 + i;
        const int nb = n0 + tx*8;
        float4 bia0 = *(const float4*)&bias[nb];
        float4 bia1 = *(const float4*)&bias[nb + 4];
        float o[8];
        o[0]=(acc[i][0]+bia0.x)*scale; o[1]=(acc[i][1]+bia0.y)*scale;
        o[2]=(acc[i][2]+bia0.z)*scale; o[3]=(acc[i][3]+bia0.w)*scale;
        o[4]=(acc[i][4]+bia1.x)*scale; o[5]=(acc[i][5]+bia1.y)*scale;
        o[6]=(acc[i][6]+bia1.z)*scale; o[7]=(acc[i][7]+bia1.w)*scale;
        if (res) {
            float4 r0 = *(const float4*)&res[(size_t)m*N + nb];
            float4 r1 = *(const float4*)&res[(size_t)m*N + nb + 4];
            o[0]+=r0.x; o[1]+=r0.y; o[2]+=r0.z; o[3]+=r0.w;
            o[4]+=r1.x; o[5]+=r1.y; o[6]+=r1.z; o[7]+=r1.w;
        }
        if (relu) {
#pragma unroll
            for (int j = 0; j < 8; j++) o[j] = fmaxf(o[j], 0.f);
        }
        *(float4*)&C[(size_t)m*N + nb]     = make_float4(o[0],o[1],o[2],o[3]);
        *(float4*)&C[(size_t)m*N + nb + 4] = make_float4(o[4],o[5],o[6],o[7]);
    }
}

// ---------------- attention scores: S[bh,i,j] = sum_d q[b,i,h*64+d]*k[b,j,h*64+d]
__global__ __launch_bounds__(256) void attn_scores(
    const float* __restrict__ q, const float* __restrict__ k, float* __restrict__ s)
{
    __shared__ float Qs[64][65];
    __shared__ float Ks[64][65];
    const int bh = blockIdx.z;
    const int b = bh >> 4, h = bh & 15;
    const int i0 = blockIdx.y * 64, j0 = blockIdx.x * 64;
    const int tid = threadIdx.x;

#pragma unroll
    for (int p = 0; p < 4; p++) {
        int lin = p * 256 + tid;
        int row = lin >> 4;
        int c = (lin & 15) << 2;
        float4 v = *(const float4*)&q[((size_t)(b*SEQ + i0 + row))*DIM + h*DH + c];
        Qs[row][c]=v.x; Qs[row][c+1]=v.y; Qs[row][c+2]=v.z; Qs[row][c+3]=v.w;
        float4 w = *(const float4*)&k[((size_t)(b*SEQ + j0 + row))*DIM + h*DH + c];
        Ks[row][c]=w.x; Ks[row][c+1]=w.y; Ks[row][c+2]=w.z; Ks[row][c+3]=w.w;
    }
    __syncthreads();

    const int tx = tid & 15, ty = tid >> 4;
    float acc[4][4];
#pragma unroll
    for (int i = 0; i < 4; i++)
#pragma unroll
        for (int j = 0; j < 4; j++) acc[i][j] = 0.f;

#pragma unroll 8
    for (int kk = 0; kk < 64; kk++) {
        float a[4], b4[4];
#pragma unroll
        for (int r = 0; r < 4; r++) a[r]  = Qs[ty*4 + r][kk];
#pragma unroll
        for (int c = 0; c < 4; c++) b4[c] = Ks[tx*4 + c][kk];
#pragma unroll
        for (int r = 0; r < 4; r++)
#pragma unroll
            for (int c = 0; c < 4; c++)
                acc[r][c] = fmaf(a[r], b4[c], acc[r][c]);
    }

#pragma unroll
    for (int r = 0; r < 4; r++) {
        size_t idx = ((size_t)bh*SEQ + i0 + ty*4 + r)*SEQ + j0 + tx*4;
        *(float4*)&s[idx] = make_float4(acc[r][0], acc[r][1], acc[r][2], acc[r][3]);
    }
}

// ---------------- softmax over rows of s, with last column masked to -inf → 0
__global__ __launch_bounds__(256) void softmax_mask_last(float* __restrict__ s)
{
    __shared__ float sm[8];
    const size_t base = (size_t)blockIdx.x * SEQ;
    const int tid = threadIdx.x;
    const int lane = tid & 31, wid = tid >> 5;

    float4 v = *(const float4*)&s[base + tid*4];
    const bool haslast = (tid == 255);
    if (haslast) v.w = -INFINITY;

    float m = fmaxf(fmaxf(v.x, v.y), fmaxf(v.z, v.w));
#pragma unroll
    for (int o = 16; o; o >>= 1) m = fmaxf(m, __shfl_xor_sync(0xffffffffu, m, o));
    if (lane == 0) sm[wid] = m;
    __syncthreads();
    if (tid == 0) {
        float t = sm[0];
#pragma unroll
        for (int i = 1; i < 8; i++) t = fmaxf(t, sm[i]);
        sm[0] = t;
    }
    __syncthreads();
    const float mall = sm[0];
    __syncthreads();

    float e0 = __expf(v.x - mall);
    float e1 = __expf(v.y - mall);
    float e2 = __expf(v.z - mall);
    float e3 = haslast ? 0.f : __expf(v.w - mall);
    float ssum = e0 + e1 + e2 + e3;
#pragma unroll
    for (int o = 16; o; o >>= 1) ssum += __shfl_xor_sync(0xffffffffu, ssum, o);
    if (lane == 0) sm[wid] = ssum;
    __syncthreads();
    if (tid == 0) {
        float t = 0.f;
#pragma unroll
        for (int i = 0; i < 8; i++) t += sm[i];
        sm[0] = t;
    }
    __syncthreads();
    const float inv = 1.f / sm[0];

    *(float4*)&s[base + tid*4] = make_float4(e0*inv, e1*inv, e2*inv, e3*inv);
}

// ---------------- PV: o[b,i,h*64+d] = sum_j P[bh,i,j] * v[b,j,h*64+d]
__global__ __launch_bounds__(256) void attn_pv(
    const float* __restrict__ p, const float* __restrict__ v, float* __restrict__ o)
{
    __shared__ float Ps[64][65];
    __shared__ float Vs[64][64];
    const int bh = blockIdx.y;
    const int b = bh >> 4, h = bh & 15;
    const int i0 = blockIdx.x * 64;
    const int tid = threadIdx.x;
    const int tx = tid & 15, ty = tid >> 4;

    float acc[4][4];
#pragma unroll
    for (int i = 0; i < 4; i++)
#pragma unroll
        for (int j = 0; j < 4; j++) acc[i][j] = 0.f;

    for (int j0 = 0; j0 < SEQ; j0 += 64) {
#pragma unroll
        for (int q4 = 0; q4 < 4; q4++) {
            int lin = q4 * 256 + tid;
            int row = lin >> 4;
            int c = (lin & 15) << 2;
            float4 pv = *(const float4*)&p[((size_t)bh*SEQ + i0 + row)*SEQ + j0 + c];
            Ps[row][c]=pv.x; Ps[row][c+1]=pv.y; Ps[row][c+2]=pv.z; Ps[row][c+3]=pv.w;
            float4 vv = *(const float4*)&v[((size_t)(b*SEQ + j0 + row))*DIM + h*DH + c];
            *(float4*)&Vs[row][c] = vv;
        }
        __syncthreads();
#pragma unroll 8
        for (int jj = 0; jj < 64; jj++) {
            float a[4];
#pragma unroll
            for (int r = 0; r < 4; r++) a[r] = Ps[ty*4 + r][jj];
            float4 bv = *(const float4*)&Vs[jj][tx*4];
#pragma unroll
            for (int r = 0; r < 4; r++) {
                acc[r][0] = fmaf(a[r], bv.x, acc[r][0]);
                acc[r][1] = fmaf(a[r], bv.y, acc[r][1]);
                acc[r][2] = fmaf(a[r], bv.z, acc[r][2]);
                acc[r][3] = fmaf(a[r], bv.w, acc[r][3]);
            }
        }
        __syncthreads();
    }

#pragma unroll
    for (int r = 0; r < 4; r++) {
        size_t idx = ((size_t)(b*SEQ + i0 + ty*4 + r))*DIM + h*DH + tx*4;
        *(float4*)&o[idx] = make_float4(acc[r][0], acc[r][1], acc[r][2], acc[r][3]);
    }
}

// ---------------- row layernorm: out = (x-mean)*rsqrt(var+eps)*g + b
__global__ __launch_bounds__(256) void layernorm_row(
    const float* __restrict__ in, float* __restrict__ out,
    const float* __restrict__ g, const float* __restrict__ be)
{
    __shared__ float sm[8], sq[8];
    const size_t base = (size_t)blockIdx.x * DIM;
    const int tid = threadIdx.x;
    const int lane = tid & 31, wid = tid >> 5;

    float4 v = *(const float4*)&in[base + tid*4];
    float s  = v.x + v.y + v.z + v.w;
    float s2 = v.x*v.x + v.y*v.y + v.z*v.z + v.w*v.w;
#pragma unroll
    for (int o = 16; o; o >>= 1) {
        s  += __shfl_xor_sync(0xffffffffu, s,  o);
        s2 += __shfl_xor_sync(0xffffffffu, s2, o);
    }
    if (lane == 0) { sm[wid] = s; sq[wid] = s2; }
    __syncthreads();
    if (tid == 0) {
        float t = 0.f, t2 = 0.f;
#pragma unroll
        for (int i = 0; i < 8; i++) { t += sm[i]; t2 += sq[i]; }
        sm[0] = t; sq[0] = t2;
    }
    __syncthreads();
    const float mean = sm[0] * (1.f / DIM);
    const float var  = sq[0] * (1.f / DIM) - mean * mean;
    const float r = rsqrtf(var + 1e-5f);

    float4 gg = *(const float4*)&g[tid*4];
    float4 bb = *(const float4*)&be[tid*4];
    float4 o4;
    o4.x = (v.x - mean) * r * gg.x + bb.x;
    o4.y = (v.y - mean) * r * gg.y + bb.y;
    o4.z = (v.z - mean) * r * gg.z + bb.z;
    o4.w = (v.w - mean) * r * gg.w + bb.w;
    *(float4*)&out[base + tid*4] = o4;
}

// ---------------- launcher -------------------------------------------------
extern "C" void kernel_launch(void* const* d_in, const int* in_sizes, int n_in,
                              void* d_out, int out_size)
{
    const float* x  = (const float*)d_in[0];
    const float* Wq = (const float*)d_in[1];
    const float* bq = (const float*)d_in[2];
    const float* Wk = (const float*)d_in[3];
    const float* bk = (const float*)d_in[4];
    const float* Wv = (const float*)d_in[5];
    const float* bv = (const float*)d_in[6];
    const float* Wf = (const float*)d_in[7];
    const float* bf = (const float*)d_in[8];
    const float* W1 = (const float*)d_in[9];
    const float* b1 = (const float*)d_in[10];
    const float* W2 = (const float*)d_in[11];
    const float* b2 = (const float*)d_in[12];
    const float* g1 = (const float*)d_in[13];
    const float* be1= (const float*)d_in[14];
    const float* g2 = (const float*)d_in[15];
    const float* be2= (const float*)d_in[16];

    float* out   = (float*)d_out;                      // [8,1024,1024]
    float* score = out + (size_t)MTOK * DIM;           // [8,16,1024,1024]

    float *pq, *pk, *pv, *pattn, *ph1, *pffn;
    cudaGetSymbolAddress((void**)&pq,    g_q);
    cudaGetSymbolAddress((void**)&pk,    g_k);
    cudaGetSymbolAddress((void**)&pv,    g_v);
    cudaGetSymbolAddress((void**)&pattn, g_attn);
    cudaGetSymbolAddress((void**)&ph1,   g_h1);
    cudaGetSymbolAddress((void**)&pffn,  g_ffn);

    const float inv_sqrt_dh = 0.125f; // 1/sqrt(64)

    // QKV projections
    gemm_nt<<<dim3(DIM/128, MTOK/128), 256>>>(x, Wq, bq, nullptr, pq, MTOK, DIM, DIM, inv_sqrt_dh, 0);
    gemm_nt<<<dim3(DIM/128, MTOK/128), 256>>>(x, Wk, bk, nullptr, pk, MTOK, DIM, DIM, 1.f, 0);
    gemm_nt<<<dim3(DIM/128, MTOK/128), 256>>>(x, Wv, bv, nullptr, pv, MTOK, DIM, DIM, 1.f, 0);

    // scores (raw) -> score region of d_out, softmax in place, PV reads it back
    attn_scores<<<dim3(SEQ/64, SEQ/64, BSZ*NH), 256>>>(pq, pk, score);
    softmax_mask_last<<<BSZ*NH*SEQ, 256>>>(score);
    attn_pv<<<dim3(SEQ/64, BSZ*NH), 256>>>(score, pv, pattn);

    // output projection + residual, then LN1
    gemm_nt<<<dim3(DIM/128, MTOK/128), 256>>>(pattn, Wf, bf, x, ph1, MTOK, DIM, DIM, 1.f, 0);
    layernorm_row<<<MTOK, 256>>>(ph1, ph1, g1, be1);

    // FFN
    gemm_nt<<<dim3(FFD/128, MTOK/128), 256>>>(ph1, W1, b1, nullptr, pffn, MTOK, FFD, DIM, 1.f, 1);
    gemm_nt<<<dim3(DIM/128, MTOK/128), 256>>>(pffn, W2, b2, ph1, pq, MTOK, DIM, FFD, 1.f, 0);
    layernorm_row<<<MTOK, 256>>>(pq, out, g2, be2);
}